// round 15
// baseline (speedup 1.0000x reference)
#include <cuda_runtime.h>
#include <cuda_fp16.h>
#include <cstdint>

#define NCH 1089
#define NG  76
#define TSTRW 68
#define T_WORDS (256*TSTRW)
#define BSTRW 36
#define B_WORDS (128*BSTRW)
#define BW  T_WORDS
#define OW  (BW + 2*B_WORDS)
#define SMEM_WORDS (OW + 128)
#define SMEM_BYTES (SMEM_WORDS*4)

__device__ float g_part[NG * 256 * 128];   // [g][m][n]

__device__ __forceinline__ uint32_t smem_u32(const void* p) {
    uint32_t a;
    asm("{ .reg .u64 t; cvta.to.shared.u64 t, %1; cvt.u32.u64 %0, t; }" : "=r"(a) : "l"(p));
    return a;
}
#define CP16(dst, src) asm volatile("cp.async.cg.shared.global [%0], [%1], 16;" :: "r"(dst), "l"(src))
#define CP_COMMIT()    asm volatile("cp.async.commit_group;")

// ---------------------------------------------------------------------------
__global__ void __launch_bounds__(512, 1)
tfn_gemm(const float* __restrict__ audio, const float* __restrict__ video,
         const float* __restrict__ text, const float* __restrict__ W1) {
    extern __shared__ uint32_t sw[];
    const uint32_t sb = smem_u32(sw);
    const int tid = threadIdx.x;
    const int w = tid >> 5, lane = tid & 31;
    const int grp = lane >> 2, tg = lane & 3;
    const int slice = blockIdx.x;            // 0/1 : 64-col N slice
    const int g     = blockIdx.y;            // 0..75 : chunk group

    const int kr = tid >> 4, c4 = tid & 15;
    const uint32_t bh0 = sb + BW * 4;

    // LDG chunk 0 -> regs
    float4 wv[4]; float4 ov = make_float4(0.f, 0.f, 0.f, 0.f);
    {
        const float* Wc = W1 + (size_t)g * 16512 + slice * 64;
        #pragma unroll
        for (int t = 0; t < 4; t++)
            wv[t] = __ldg((const float4*)(Wc + (size_t)(kr + 32 * t + 1) * 128 + c4 * 4));
        if (tid < 16) ov = __ldg((const float4*)(Wc + tid * 4));
    }

    // build T fp16 in smem once
    {
        const float* src = text + (size_t)(tid >> 1) * 128 + (tid & 1) * 64;
        uint32_t dst = sb + (uint32_t)((tid >> 1) * TSTRW + (tid & 1) * 32) * 4;
        #pragma unroll
        for (int j = 0; j < 16; j++) {
            float4 v = __ldg((const float4*)(src + j * 4));
            uint32_t p0, p1;
            asm("cvt.rn.f16x2.f32 %0, %1, %2;" : "=r"(p0) : "f"(v.y), "f"(v.x));
            asm("cvt.rn.f16x2.f32 %0, %1, %2;" : "=r"(p1) : "f"(v.w), "f"(v.z));
            asm volatile("st.shared.v2.b32 [%0], {%1,%2};"
                :: "r"(dst + j * 8), "r"(p0), "r"(p1) : "memory");
        }
    }

    // STS chunk 0 -> buf 0
    {
        #pragma unroll
        for (int t = 0; t < 4; t++) {
            uint32_t p0, p1;
            asm("cvt.rn.f16x2.f32 %0, %1, %2;" : "=r"(p0) : "f"(wv[t].y), "f"(wv[t].x));
            asm("cvt.rn.f16x2.f32 %0, %1, %2;" : "=r"(p1) : "f"(wv[t].w), "f"(wv[t].z));
            asm volatile("st.shared.v2.b32 [%0], {%1,%2};"
                :: "r"(bh0 + (uint32_t)((kr + 32 * t) * BSTRW + 2 * c4) * 4),
                   "r"(p0), "r"(p1) : "memory");
        }
        if (tid < 16)
            asm volatile("st.shared.v4.f32 [%0], {%1,%2,%3,%4};"
                :: "r"(sb + (uint32_t)(OW + tid * 4) * 4),
                   "f"(ov.x), "f"(ov.y), "f"(ov.z), "f"(ov.w) : "memory");
    }
    __syncthreads();

    const int nch = (NCH - g + NG - 1) / NG;   // 14 or 15

    if (nch > 1) {
        const float* Wn = W1 + (size_t)(g + NG) * 16512 + slice * 64;
        #pragma unroll
        for (int t = 0; t < 4; t++)
            wv[t] = __ldg((const float4*)(Wn + (size_t)(kr + 32 * t + 1) * 128 + c4 * 4));
        if (tid < 16) ov = __ldg((const float4*)(Wn + tid * 4));
    }

    const int row0 = (w << 4) + grp;
    const uint32_t aAddr = sb + (uint32_t)((w * 16 + (lane & 15)) * TSTRW) * 4
                         + ((uint32_t)(lane >> 4) << 4);

    float acc[8][4];
    #pragma unroll
    for (int nt = 0; nt < 8; nt++)
        #pragma unroll
        for (int e = 0; e < 4; e++) acc[nt][e] = 0.0f;

    for (int i = 0; i < nch; i++) {
        const int cc = g + i * NG;
        const int buf = i & 1;

        if (i + 1 < nch) {   // STS chunk i+1 -> buf^1 (hidden under MMA(i))
            const uint32_t bn = bh0 + (uint32_t)(buf ^ 1) * (B_WORDS * 4);
            #pragma unroll
            for (int t = 0; t < 4; t++) {
                uint32_t p0, p1;
                asm("cvt.rn.f16x2.f32 %0, %1, %2;" : "=r"(p0) : "f"(wv[t].y), "f"(wv[t].x));
                asm("cvt.rn.f16x2.f32 %0, %1, %2;" : "=r"(p1) : "f"(wv[t].w), "f"(wv[t].z));
                asm volatile("st.shared.v2.b32 [%0], {%1,%2};"
                    :: "r"(bn + (uint32_t)((kr + 32 * t) * BSTRW + 2 * c4) * 4),
                       "r"(p0), "r"(p1) : "memory");
            }
            if (tid < 16)
                asm volatile("st.shared.v4.f32 [%0], {%1,%2,%3,%4};"
                    :: "r"(sb + (uint32_t)(OW + (buf ^ 1) * 64 + tid * 4) * 4),
                       "f"(ov.x), "f"(ov.y), "f"(ov.z), "f"(ov.w) : "memory");
        }
        if (i + 2 < nch) {   // LDG chunk i+2 -> regs
            const float* Wn = W1 + (size_t)(cc + 2 * NG) * 16512 + slice * 64;
            #pragma unroll
            for (int t = 0; t < 4; t++)
                wv[t] = __ldg((const float4*)(Wn + (size_t)(kr + 32 * t + 1) * 128 + c4 * 4));
            if (tid < 16) ov = __ldg((const float4*)(Wn + tid * 4));
        }

        const int ai = cc / 33, vi = cc - ai * 33;
        float s0, s1;
        {
            float av0 = (ai == 0) ? 1.0f : __ldg(&audio[row0 * 32 + ai - 1]);
            float vv0 = (vi == 0) ? 1.0f : __ldg(&video[row0 * 32 + vi - 1]);
            float av1 = (ai == 0) ? 1.0f : __ldg(&audio[(row0 + 8) * 32 + ai - 1]);
            float vv1 = (vi == 0) ? 1.0f : __ldg(&video[(row0 + 8) * 32 + vi - 1]);
            s0 = av0 * vv0; s1 = av1 * vv1;
        }

        float tacc[8][4];
        #pragma unroll
        for (int nt = 0; nt < 8; nt++)
            #pragma unroll
            for (int e = 0; e < 4; e++) tacc[nt][e] = 0.0f;

        const uint32_t bb = bh0 + (uint32_t)buf * (B_WORDS * 4);
        #pragma unroll
        for (int kt = 0; kt < 8; kt++) {
            uint32_t a0, a1, a2, a3;
            asm volatile("ldmatrix.sync.aligned.m8n8.x4.shared.b16 {%0,%1,%2,%3}, [%4];"
                : "=r"(a0), "=r"(a1), "=r"(a2), "=r"(a3)
                : "r"(aAddr + (uint32_t)kt * 32));
            const uint32_t bRow = bb + (uint32_t)((kt * 16 + (lane & 15)) * BSTRW) * 4
                                + ((uint32_t)(lane >> 4) << 4);
            #pragma unroll
            for (int np = 0; np < 4; np++) {
                uint32_t r0, r1, r2, r3;
                asm volatile("ldmatrix.sync.aligned.m8n8.x4.trans.shared.b16 {%0,%1,%2,%3}, [%4];"
                    : "=r"(r0), "=r"(r1), "=r"(r2), "=r"(r3)
                    : "r"(bRow + (uint32_t)np * 32));
                asm volatile(
                    "mma.sync.aligned.m16n8k16.row.col.f32.f16.f16.f32 "
                    "{%0,%1,%2,%3}, {%4,%5,%6,%7}, {%8,%9}, {%0,%1,%2,%3};"
                    : "+f"(tacc[2 * np][0]), "+f"(tacc[2 * np][1]),
                      "+f"(tacc[2 * np][2]), "+f"(tacc[2 * np][3])
                    : "r"(a0), "r"(a1), "r"(a2), "r"(a3), "r"(r0), "r"(r1));
                asm volatile(
                    "mma.sync.aligned.m16n8k16.row.col.f32.f16.f16.f32 "
                    "{%0,%1,%2,%3}, {%4,%5,%6,%7}, {%8,%9}, {%0,%1,%2,%3};"
                    : "+f"(tacc[2 * np + 1][0]), "+f"(tacc[2 * np + 1][1]),
                      "+f"(tacc[2 * np + 1][2]), "+f"(tacc[2 * np + 1][3])
                    : "r"(a0), "r"(a1), "r"(a2), "r"(a3), "r"(r2), "r"(r3));
            }
        }

        const float* on = (const float*)sw + OW + buf * 64;
        #pragma unroll
        for (int nt = 0; nt < 8; nt++) {
            float ox = on[nt * 8 + 2 * tg];
            float oy = on[nt * 8 + 2 * tg + 1];
            acc[nt][0] = fmaf(s0, tacc[nt][0] + ox, acc[nt][0]);
            acc[nt][1] = fmaf(s0, tacc[nt][1] + oy, acc[nt][1]);
            acc[nt][2] = fmaf(s1, tacc[nt][2] + ox, acc[nt][2]);
            acc[nt][3] = fmaf(s1, tacc[nt][3] + oy, acc[nt][3]);
        }
        __syncthreads();
    }

    float* part = g_part + (size_t)g * 32768;
    #pragma unroll
    for (int nt = 0; nt < 8; nt++) {
        int col = slice * 64 + nt * 8 + 2 * tg;
        *(float2*)&part[row0 * 128 + col]       = make_float2(acc[nt][0], acc[nt][1]);
        *(float2*)&part[(row0 + 8) * 128 + col] = make_float2(acc[nt][2], acc[nt][3]);
    }
}

// ---------------------------------------------------------------------------
// epi v6: one wave, 152 CTAs x 1024 threads. CTA b -> rows b and b+152.
// 16 buckets/row in the reduce; 4-way k-split in L2.
#define EPI_FLOATS (16384 + 4096 + 256 + 1024 + 16)
#define EPI_BYTES  (EPI_FLOATS * 4)
__global__ void __launch_bounds__(1024)
epi(const float* __restrict__ b1, const float* __restrict__ W2,
    const float* __restrict__ b2, const float* __restrict__ W3,
    const float* __restrict__ b3, float* __restrict__ out) {
    extern __shared__ float smf[];
    float* W2s  = smf;            // 16384
    float* ps   = smf + 16384;    // [2 rows][16 buckets][128]
    float* h1s  = ps + 4096;      // [2][128]
    float* psum = h1s + 256;      // [2 rows][4 kq][128]
    float* red  = psum + 1024;    // [8]
    const int t = threadIdx.x;
    const int r0 = blockIdx.x;
    const int r1 = blockIdx.x + 152;
    const bool has2 = (r1 < 256);

    {   // stage W2 (overlaps reduce)
        const char* src = (const char*)W2;
        const uint32_t dW = smem_u32(W2s);
        #pragma unroll
        for (int i = 0; i < 4; i++) {
            int task = t + (i << 10);
            CP16(dW + (uint32_t)task * 16, src + (size_t)task * 16);
        }
        CP_COMMIT();
    }

    {   // reduce: rs = row (t>>9), s = bucket 0..15, q = col quad 0..31
        const int q = t & 31, s = (t >> 5) & 15, rs = t >> 9;
        const int r = rs ? (has2 ? r1 : r0) : r0;
        float4 sum = make_float4(0.f, 0.f, 0.f, 0.f);
        const float* base = g_part + (size_t)r * 128 + q * 4;
        #pragma unroll
        for (int gg = s; gg < NG; gg += 16) {
            float4 v = __ldg((const float4*)(base + (size_t)gg * 32768));
            sum.x += v.x; sum.y += v.y; sum.z += v.z; sum.w += v.w;
        }
        *(float4*)&ps[(rs * 16 + s) * 128 + q * 4] = sum;
    }
    asm volatile("cp.async.wait_group 0;");
    __syncthreads();

    // L1 bias + relu (256 threads: 2 rows x 128 cols)
    if (t < 256) {
        const int row = t >> 7, p = t & 127;
        float sum = __ldg(&b1[p]);
        #pragma unroll
        for (int s = 0; s < 16; s++) sum += ps[(row * 16 + s) * 128 + p];
        h1s[row * 128 + p] = fmaxf(sum, 0.0f);
    }
    __syncthreads();

    // L2: all 1024 threads: row = t>>9, k-quarter = (t>>7)&3, p = t&127
    {
        const int row = t >> 9, kq = (t >> 7) & 3, p = t & 127, k0 = kq << 5;
        const float* hr = h1s + row * 128;
        float a0 = 0.0f, a1 = 0.0f;
        #pragma unroll
        for (int k = 0; k < 32; k += 2) {
            a0 = fmaf(hr[k0 + k],     W2s[(k0 + k) * 128 + p],     a0);
            a1 = fmaf(hr[k0 + k + 1], W2s[(k0 + k + 1) * 128 + p], a1);
        }
        psum[(row * 4 + kq) * 128 + p] = a0 + a1;
    }
    __syncthreads();

    // L3 (256 threads: 2 rows x 128 p)
    if (t < 256) {
        const int row = t >> 7, p = t & 127;
        float h2 = fmaxf(psum[(row * 4 + 0) * 128 + p] + psum[(row * 4 + 1) * 128 + p]
                       + psum[(row * 4 + 2) * 128 + p] + psum[(row * 4 + 3) * 128 + p]
                       + __ldg(&b2[p]), 0.0f) * __ldg(&W3[p]);
        #pragma unroll
        for (int o = 16; o > 0; o >>= 1) h2 += __shfl_down_sync(0xffffffff, h2, o);
        if ((t & 31) == 0) red[t >> 5] = h2;
    }
    __syncthreads();
    if (t == 0)
        out[r0] = red[0] + red[1] + red[2] + red[3] + __ldg(&b3[0]);
    if (t == 128 && has2)
        out[r1] = red[4] + red[5] + red[6] + red[7] + __ldg(&b3[0]);
}

// ---------------------------------------------------------------------------
extern "C" void kernel_launch(void* const* d_in, const int* in_sizes, int n_in,
                              void* d_out, int out_size) {
    (void)in_sizes; (void)n_in; (void)out_size;
    const float* audio = (const float*)d_in[0];
    const float* video = (const float*)d_in[1];
    const float* text  = (const float*)d_in[2];
    const float* W1    = (const float*)d_in[3];
    const float* b1    = (const float*)d_in[4];
    const float* W2    = (const float*)d_in[5];
    const float* b2    = (const float*)d_in[6];
    const float* W3    = (const float*)d_in[7];
    const float* b3    = (const float*)d_in[8];
    float* out = (float*)d_out;

    cudaFuncSetAttribute(tfn_gemm, cudaFuncAttributeMaxDynamicSharedMemorySize,
                         SMEM_BYTES);
    cudaFuncSetAttribute(epi, cudaFuncAttributeMaxDynamicSharedMemorySize,
                         EPI_BYTES);

    dim3 grid(2, NG);   // 152 CTAs = one wave
    tfn_gemm<<<grid, 512, SMEM_BYTES>>>(audio, video, text, W1);
    epi<<<152, 1024, EPI_BYTES>>>(b1, W2, b2, W3, b3, out);
}

// round 16
// speedup vs baseline: 1.0760x; 1.0760x over previous
#include <cuda_runtime.h>
#include <cuda_fp16.h>
#include <cstdint>

#define NCH 1089
#define NG  76
#define TSTRW 68
#define T_WORDS (256*TSTRW)
#define BSTRW 36
#define B_WORDS (128*BSTRW)
#define BW  T_WORDS
#define OW  (BW + 2*B_WORDS)
#define SMEM_WORDS (OW + 128)
#define SMEM_BYTES (SMEM_WORDS*4)

__device__ uint32_t g_parth[NG * 256 * 64];   // [g][m][n/2] half2, 5 MB

__device__ __forceinline__ uint32_t smem_u32(const void* p) {
    uint32_t a;
    asm("{ .reg .u64 t; cvta.to.shared.u64 t, %1; cvt.u32.u64 %0, t; }" : "=r"(a) : "l"(p));
    return a;
}
#define CP16(dst, src) asm volatile("cp.async.cg.shared.global [%0], [%1], 16;" :: "r"(dst), "l"(src))
#define CP_COMMIT()    asm volatile("cp.async.commit_group;")

// ---------------------------------------------------------------------------
__global__ void __launch_bounds__(512, 1)
tfn_gemm(const float* __restrict__ audio, const float* __restrict__ video,
         const float* __restrict__ text, const float* __restrict__ W1) {
    extern __shared__ uint32_t sw[];
    const uint32_t sb = smem_u32(sw);
    const int tid = threadIdx.x;
    const int w = tid >> 5, lane = tid & 31;
    const int grp = lane >> 2, tg = lane & 3;
    const int slice = blockIdx.x;            // 0/1 : 64-col N slice
    const int g     = blockIdx.y;            // 0..75 : chunk group

    const int kr = tid >> 4, c4 = tid & 15;
    const uint32_t bh0 = sb + BW * 4;

    // LDG chunk 0 -> regs
    float4 wv[4]; float4 ov = make_float4(0.f, 0.f, 0.f, 0.f);
    {
        const float* Wc = W1 + (size_t)g * 16512 + slice * 64;
        #pragma unroll
        for (int t = 0; t < 4; t++)
            wv[t] = __ldg((const float4*)(Wc + (size_t)(kr + 32 * t + 1) * 128 + c4 * 4));
        if (tid < 16) ov = __ldg((const float4*)(Wc + tid * 4));
    }

    // build T fp16 in smem once
    {
        const float* src = text + (size_t)(tid >> 1) * 128 + (tid & 1) * 64;
        uint32_t dst = sb + (uint32_t)((tid >> 1) * TSTRW + (tid & 1) * 32) * 4;
        #pragma unroll
        for (int j = 0; j < 16; j++) {
            float4 v = __ldg((const float4*)(src + j * 4));
            uint32_t p0, p1;
            asm("cvt.rn.f16x2.f32 %0, %1, %2;" : "=r"(p0) : "f"(v.y), "f"(v.x));
            asm("cvt.rn.f16x2.f32 %0, %1, %2;" : "=r"(p1) : "f"(v.w), "f"(v.z));
            asm volatile("st.shared.v2.b32 [%0], {%1,%2};"
                :: "r"(dst + j * 8), "r"(p0), "r"(p1) : "memory");
        }
    }

    // STS chunk 0 -> buf 0
    {
        #pragma unroll
        for (int t = 0; t < 4; t++) {
            uint32_t p0, p1;
            asm("cvt.rn.f16x2.f32 %0, %1, %2;" : "=r"(p0) : "f"(wv[t].y), "f"(wv[t].x));
            asm("cvt.rn.f16x2.f32 %0, %1, %2;" : "=r"(p1) : "f"(wv[t].w), "f"(wv[t].z));
            asm volatile("st.shared.v2.b32 [%0], {%1,%2};"
                :: "r"(bh0 + (uint32_t)((kr + 32 * t) * BSTRW + 2 * c4) * 4),
                   "r"(p0), "r"(p1) : "memory");
        }
        if (tid < 16)
            asm volatile("st.shared.v4.f32 [%0], {%1,%2,%3,%4};"
                :: "r"(sb + (uint32_t)(OW + tid * 4) * 4),
                   "f"(ov.x), "f"(ov.y), "f"(ov.z), "f"(ov.w) : "memory");
    }
    __syncthreads();

    const int nch = (NCH - g + NG - 1) / NG;   // 14 or 15

    if (nch > 1) {
        const float* Wn = W1 + (size_t)(g + NG) * 16512 + slice * 64;
        #pragma unroll
        for (int t = 0; t < 4; t++)
            wv[t] = __ldg((const float4*)(Wn + (size_t)(kr + 32 * t + 1) * 128 + c4 * 4));
        if (tid < 16) ov = __ldg((const float4*)(Wn + tid * 4));
    }

    const int row0 = (w << 4) + grp;
    const uint32_t aAddr = sb + (uint32_t)((w * 16 + (lane & 15)) * TSTRW) * 4
                         + ((uint32_t)(lane >> 4) << 4);

    float acc[8][4];
    #pragma unroll
    for (int nt = 0; nt < 8; nt++)
        #pragma unroll
        for (int e = 0; e < 4; e++) acc[nt][e] = 0.0f;

    for (int i = 0; i < nch; i++) {
        const int cc = g + i * NG;
        const int buf = i & 1;

        if (i + 1 < nch) {   // STS chunk i+1 -> buf^1 (hidden under MMA(i))
            const uint32_t bn = bh0 + (uint32_t)(buf ^ 1) * (B_WORDS * 4);
            #pragma unroll
            for (int t = 0; t < 4; t++) {
                uint32_t p0, p1;
                asm("cvt.rn.f16x2.f32 %0, %1, %2;" : "=r"(p0) : "f"(wv[t].y), "f"(wv[t].x));
                asm("cvt.rn.f16x2.f32 %0, %1, %2;" : "=r"(p1) : "f"(wv[t].w), "f"(wv[t].z));
                asm volatile("st.shared.v2.b32 [%0], {%1,%2};"
                    :: "r"(bn + (uint32_t)((kr + 32 * t) * BSTRW + 2 * c4) * 4),
                       "r"(p0), "r"(p1) : "memory");
            }
            if (tid < 16)
                asm volatile("st.shared.v4.f32 [%0], {%1,%2,%3,%4};"
                    :: "r"(sb + (uint32_t)(OW + (buf ^ 1) * 64 + tid * 4) * 4),
                       "f"(ov.x), "f"(ov.y), "f"(ov.z), "f"(ov.w) : "memory");
        }
        if (i + 2 < nch) {   // LDG chunk i+2 -> regs
            const float* Wn = W1 + (size_t)(cc + 2 * NG) * 16512 + slice * 64;
            #pragma unroll
            for (int t = 0; t < 4; t++)
                wv[t] = __ldg((const float4*)(Wn + (size_t)(kr + 32 * t + 1) * 128 + c4 * 4));
            if (tid < 16) ov = __ldg((const float4*)(Wn + tid * 4));
        }

        const int ai = cc / 33, vi = cc - ai * 33;
        float s0, s1;
        {
            float av0 = (ai == 0) ? 1.0f : __ldg(&audio[row0 * 32 + ai - 1]);
            float vv0 = (vi == 0) ? 1.0f : __ldg(&video[row0 * 32 + vi - 1]);
            float av1 = (ai == 0) ? 1.0f : __ldg(&audio[(row0 + 8) * 32 + ai - 1]);
            float vv1 = (vi == 0) ? 1.0f : __ldg(&video[(row0 + 8) * 32 + vi - 1]);
            s0 = av0 * vv0; s1 = av1 * vv1;
        }

        float tacc[8][4];
        #pragma unroll
        for (int nt = 0; nt < 8; nt++)
            #pragma unroll
            for (int e = 0; e < 4; e++) tacc[nt][e] = 0.0f;

        const uint32_t bb = bh0 + (uint32_t)buf * (B_WORDS * 4);
        #pragma unroll
        for (int kt = 0; kt < 8; kt++) {
            uint32_t a0, a1, a2, a3;
            asm volatile("ldmatrix.sync.aligned.m8n8.x4.shared.b16 {%0,%1,%2,%3}, [%4];"
                : "=r"(a0), "=r"(a1), "=r"(a2), "=r"(a3)
                : "r"(aAddr + (uint32_t)kt * 32));
            const uint32_t bRow = bb + (uint32_t)((kt * 16 + (lane & 15)) * BSTRW) * 4
                                + ((uint32_t)(lane >> 4) << 4);
            #pragma unroll
            for (int np = 0; np < 4; np++) {
                uint32_t r0, r1, r2, r3;
                asm volatile("ldmatrix.sync.aligned.m8n8.x4.trans.shared.b16 {%0,%1,%2,%3}, [%4];"
                    : "=r"(r0), "=r"(r1), "=r"(r2), "=r"(r3)
                    : "r"(bRow + (uint32_t)np * 32));
                asm volatile(
                    "mma.sync.aligned.m16n8k16.row.col.f32.f16.f16.f32 "
                    "{%0,%1,%2,%3}, {%4,%5,%6,%7}, {%8,%9}, {%0,%1,%2,%3};"
                    : "+f"(tacc[2 * np][0]), "+f"(tacc[2 * np][1]),
                      "+f"(tacc[2 * np][2]), "+f"(tacc[2 * np][3])
                    : "r"(a0), "r"(a1), "r"(a2), "r"(a3), "r"(r0), "r"(r1));
                asm volatile(
                    "mma.sync.aligned.m16n8k16.row.col.f32.f16.f16.f32 "
                    "{%0,%1,%2,%3}, {%4,%5,%6,%7}, {%8,%9}, {%0,%1,%2,%3};"
                    : "+f"(tacc[2 * np + 1][0]), "+f"(tacc[2 * np + 1][1]),
                      "+f"(tacc[2 * np + 1][2]), "+f"(tacc[2 * np + 1][3])
                    : "r"(a0), "r"(a1), "r"(a2), "r"(a3), "r"(r2), "r"(r3));
            }
        }

        const float* on = (const float*)sw + OW + buf * 64;
        #pragma unroll
        for (int nt = 0; nt < 8; nt++) {
            float ox = on[nt * 8 + 2 * tg];
            float oy = on[nt * 8 + 2 * tg + 1];
            acc[nt][0] = fmaf(s0, tacc[nt][0] + ox, acc[nt][0]);
            acc[nt][1] = fmaf(s0, tacc[nt][1] + oy, acc[nt][1]);
            acc[nt][2] = fmaf(s1, tacc[nt][2] + ox, acc[nt][2]);
            acc[nt][3] = fmaf(s1, tacc[nt][3] + oy, acc[nt][3]);
        }
        __syncthreads();
    }

    // split-K partial store as half2: [g][m][n/2]
    uint32_t* part = g_parth + (size_t)g * 16384;
    #pragma unroll
    for (int nt = 0; nt < 8; nt++) {
        int colp = slice * 32 + nt * 4 + tg;
        uint32_t p0, p1;
        asm("cvt.rn.f16x2.f32 %0, %1, %2;" : "=r"(p0) : "f"(acc[nt][1]), "f"(acc[nt][0]));
        asm("cvt.rn.f16x2.f32 %0, %1, %2;" : "=r"(p1) : "f"(acc[nt][3]), "f"(acc[nt][2]));
        part[row0 * 64 + colp]       = p0;
        part[(row0 + 8) * 64 + colp] = p1;
    }
}

// ---------------------------------------------------------------------------
// epi v7: one wave, 152 CTAs x 1024 threads, half2 partials (5 MB read).
// CTA b -> rows b, b+152. 32 buckets/row; L2 4-way k-split; shuffle L3.
#define EPI_FLOATS (16384 + 8192 + 256 + 1024 + 16)
#define EPI_BYTES  (EPI_FLOATS * 4)
__global__ void __launch_bounds__(1024)
epi(const float* __restrict__ b1, const float* __restrict__ W2,
    const float* __restrict__ b2, const float* __restrict__ W3,
    const float* __restrict__ b3, float* __restrict__ out) {
    extern __shared__ float smf[];
    float* W2s  = smf;            // 16384
    float* ps   = smf + 16384;    // [2 rows][32 buckets][128]
    float* h1s  = ps + 8192;      // [2][128]
    float* psum = h1s + 256;      // [2 rows][4 kq][128]
    float* red  = psum + 1024;    // [8]
    const int t = threadIdx.x;
    const int r0 = blockIdx.x;
    const int r1 = blockIdx.x + 152;
    const bool has2 = (r1 < 256);

    {   // stage W2 (overlaps reduce)
        const char* src = (const char*)W2;
        const uint32_t dW = smem_u32(W2s);
        #pragma unroll
        for (int i = 0; i < 4; i++) {
            int task = t + (i << 10);
            CP16(dW + (uint32_t)task * 16, src + (size_t)task * 16);
        }
        CP_COMMIT();
    }

    {   // reduce: rs = row (t>>9), s = bucket 0..31, q = col octet 0..15
        const int q = t & 15, s = (t >> 4) & 31, rs = t >> 9;
        const int r = rs ? (has2 ? r1 : r0) : r0;
        float sum[8];
        #pragma unroll
        for (int e = 0; e < 8; e++) sum[e] = 0.0f;
        const uint32_t* base = g_parth + (size_t)r * 64 + q * 4;
        for (int gg = s; gg < NG; gg += 32) {
            uint4 v = __ldg((const uint4*)(base + (size_t)gg * 16384));
            float2 f0 = __half22float2(*(__half2*)&v.x);
            float2 f1 = __half22float2(*(__half2*)&v.y);
            float2 f2 = __half22float2(*(__half2*)&v.z);
            float2 f3 = __half22float2(*(__half2*)&v.w);
            sum[0] += f0.x; sum[1] += f0.y; sum[2] += f1.x; sum[3] += f1.y;
            sum[4] += f2.x; sum[5] += f2.y; sum[6] += f3.x; sum[7] += f3.y;
        }
        float* dst = &ps[(rs * 32 + s) * 128 + q * 8];
        *(float4*)dst       = make_float4(sum[0], sum[1], sum[2], sum[3]);
        *(float4*)(dst + 4) = make_float4(sum[4], sum[5], sum[6], sum[7]);
    }
    asm volatile("cp.async.wait_group 0;");
    __syncthreads();

    // L1 bias + relu (256 threads: 2 rows x 128 cols)
    if (t < 256) {
        const int row = t >> 7, p = t & 127;
        float sum = __ldg(&b1[p]);
        #pragma unroll
        for (int s = 0; s < 32; s++) sum += ps[(row * 32 + s) * 128 + p];
        h1s[row * 128 + p] = fmaxf(sum, 0.0f);
    }
    __syncthreads();

    // L2: all 1024 threads: row = t>>9, k-quarter = (t>>7)&3, p = t&127
    {
        const int row = t >> 9, kq = (t >> 7) & 3, p = t & 127, k0 = kq << 5;
        const float* hr = h1s + row * 128;
        float a0 = 0.0f, a1 = 0.0f;
        #pragma unroll
        for (int k = 0; k < 32; k += 2) {
            a0 = fmaf(hr[k0 + k],     W2s[(k0 + k) * 128 + p],     a0);
            a1 = fmaf(hr[k0 + k + 1], W2s[(k0 + k + 1) * 128 + p], a1);
        }
        psum[(row * 4 + kq) * 128 + p] = a0 + a1;
    }
    __syncthreads();

    // L3 (256 threads: 2 rows x 128 p)
    if (t < 256) {
        const int row = t >> 7, p = t & 127;
        float h2 = fmaxf(psum[(row * 4 + 0) * 128 + p] + psum[(row * 4 + 1) * 128 + p]
                       + psum[(row * 4 + 2) * 128 + p] + psum[(row * 4 + 3) * 128 + p]
                       + __ldg(&b2[p]), 0.0f) * __ldg(&W3[p]);
        #pragma unroll
        for (int o = 16; o > 0; o >>= 1) h2 += __shfl_down_sync(0xffffffff, h2, o);
        if ((t & 31) == 0) red[t >> 5] = h2;
    }
    __syncthreads();
    if (t == 0)
        out[r0] = red[0] + red[1] + red[2] + red[3] + __ldg(&b3[0]);
    if (t == 128 && has2)
        out[r1] = red[4] + red[5] + red[6] + red[7] + __ldg(&b3[0]);
}

// ---------------------------------------------------------------------------
extern "C" void kernel_launch(void* const* d_in, const int* in_sizes, int n_in,
                              void* d_out, int out_size) {
    (void)in_sizes; (void)n_in; (void)out_size;
    const float* audio = (const float*)d_in[0];
    const float* video = (const float*)d_in[1];
    const float* text  = (const float*)d_in[2];
    const float* W1    = (const float*)d_in[3];
    const float* b1    = (const float*)d_in[4];
    const float* W2    = (const float*)d_in[5];
    const float* b2    = (const float*)d_in[6];
    const float* W3    = (const float*)d_in[7];
    const float* b3    = (const float*)d_in[8];
    float* out = (float*)d_out;

    cudaFuncSetAttribute(tfn_gemm, cudaFuncAttributeMaxDynamicSharedMemorySize,
                         SMEM_BYTES);
    cudaFuncSetAttribute(epi, cudaFuncAttributeMaxDynamicSharedMemorySize,
                         EPI_BYTES);

    dim3 grid(2, NG);   // 152 CTAs = one wave
    tfn_gemm<<<grid, 512, SMEM_BYTES>>>(audio, video, text, W1);
    epi<<<152, 1024, EPI_BYTES>>>(b1, W2, b2, W3, b3, out);
}